// round 1
// baseline (speedup 1.0000x reference)
#include <cuda_runtime.h>
#include <cstdint>

// Problem constants (from reference setup_inputs)
#define BATCH 4
#define SEQT  2048
#define DMODEL 512
#define NHEAD 8
#define HD    64
#define THREE_D (3 * DMODEL)
#define MROWS (BATCH * SEQT)        // 8192
#define MAX_R 16
#define MAX_W (2 * MAX_R + 1)       // 33

// Scratch (no cudaMalloc allowed)
__device__ float g_qkv[(size_t)BATCH * SEQT * THREE_D];   // 48 MB
__device__ float g_att[(size_t)BATCH * SEQT * DMODEL];    // 16 MB

// ---------------------------------------------------------------------------
// SGEMM: C[M,N] = A[M,K] @ B[N,K]^T + bias[N]
// A row-major [M,K], B row-major [N,K] (both K-contiguous), C row-major [M,N].
// BM=BN=128, BK=8, TM=TN=8, 256 threads. M%128==0, N%128==0, K%8==0 assumed.
// ---------------------------------------------------------------------------
__global__ __launch_bounds__(256) void sgemm_bias_kernel(
    const float* __restrict__ A, const float* __restrict__ B,
    const float* __restrict__ bias, float* __restrict__ C,
    int M, int N, int K)
{
    __shared__ float As[8][128];
    __shared__ float Bs[8][128];

    const int bm = blockIdx.y * 128;
    const int bn = blockIdx.x * 128;
    const int tid = threadIdx.x;
    const int trow = tid >> 4;   // 0..15
    const int tcol = tid & 15;   // 0..15

    // global-load mapping: one float4 of A and one of B per thread per k-tile
    const int lrow = tid >> 1;           // 0..127
    const int lk4  = (tid & 1) << 2;     // 0 or 4

    const float* Aptr = A + (size_t)(bm + lrow) * K + lk4;
    const float* Bptr = B + (size_t)(bn + lrow) * K + lk4;

    float acc[8][8];
#pragma unroll
    for (int i = 0; i < 8; i++)
#pragma unroll
        for (int j = 0; j < 8; j++) acc[i][j] = 0.0f;

    for (int k0 = 0; k0 < K; k0 += 8) {
        float4 av = *(const float4*)(Aptr + k0);
        float4 bv = *(const float4*)(Bptr + k0);

        As[lk4 + 0][lrow] = av.x;
        As[lk4 + 1][lrow] = av.y;
        As[lk4 + 2][lrow] = av.z;
        As[lk4 + 3][lrow] = av.w;
        Bs[lk4 + 0][lrow] = bv.x;
        Bs[lk4 + 1][lrow] = bv.y;
        Bs[lk4 + 2][lrow] = bv.z;
        Bs[lk4 + 3][lrow] = bv.w;
        __syncthreads();

#pragma unroll
        for (int kk = 0; kk < 8; kk++) {
            float a[8], b[8];
            // vector LDS: rows of As/Bs are contiguous
            float4 a0 = *(const float4*)&As[kk][trow * 8];
            float4 a1 = *(const float4*)&As[kk][trow * 8 + 4];
            float4 b0 = *(const float4*)&Bs[kk][tcol * 8];
            float4 b1 = *(const float4*)&Bs[kk][tcol * 8 + 4];
            a[0]=a0.x; a[1]=a0.y; a[2]=a0.z; a[3]=a0.w;
            a[4]=a1.x; a[5]=a1.y; a[6]=a1.z; a[7]=a1.w;
            b[0]=b0.x; b[1]=b0.y; b[2]=b0.z; b[3]=b0.w;
            b[4]=b1.x; b[5]=b1.y; b[6]=b1.z; b[7]=b1.w;
#pragma unroll
            for (int i = 0; i < 8; i++)
#pragma unroll
                for (int j = 0; j < 8; j++)
                    acc[i][j] += a[i] * b[j];
        }
        __syncthreads();
    }

    // epilogue: add bias, store (float4)
    const int cn = bn + tcol * 8;
    float4 bias0 = *(const float4*)(bias + cn);
    float4 bias1 = *(const float4*)(bias + cn + 4);
#pragma unroll
    for (int i = 0; i < 8; i++) {
        const int row = bm + trow * 8 + i;
        float4 o0, o1;
        o0.x = acc[i][0] + bias0.x; o0.y = acc[i][1] + bias0.y;
        o0.z = acc[i][2] + bias0.z; o0.w = acc[i][3] + bias0.w;
        o1.x = acc[i][4] + bias1.x; o1.y = acc[i][5] + bias1.y;
        o1.z = acc[i][6] + bias1.z; o1.w = acc[i][7] + bias1.w;
        *(float4*)(C + (size_t)row * N + cn)     = o0;
        *(float4*)(C + (size_t)row * N + cn + 4) = o1;
    }
}

// ---------------------------------------------------------------------------
// Band attention: one block per (q, h, b), 64 threads (one per hd lane).
// qkv layout: [B, T, 3D] with q=[0,D), k=[D,2D), v=[2D,3D); head h at h*64.
// ---------------------------------------------------------------------------
__global__ __launch_bounds__(64) void band_attn_kernel(
    const float* __restrict__ radius, float* __restrict__ out)
{
    const int q = blockIdx.x;
    const int h = blockIdx.y;
    const int b = blockIdx.z;
    const int d = threadIdx.x;  // 0..63

    // per-head radius: clip(sigmoid(r)*16, min=1)
    float rr = 16.0f / (1.0f + expf(-radius[h]));
    if (rr < 1.0f) rr = 1.0f;
    const int R = (int)floorf(rr);

    int klo = q - R; if (klo < 0) klo = 0;
    int khi = q + R; if (khi > SEQT - 1) khi = SEQT - 1;
    const int W = khi - klo + 1;   // <= 33

    const float* base = g_qkv + (size_t)b * SEQT * THREE_D;
    const float* qrow = base + (size_t)q * THREE_D + h * HD;

    __shared__ float sQ[HD];
    __shared__ float sP[MAX_W];
    __shared__ float sS[MAX_W];

    sQ[d] = qrow[d];
    __syncthreads();

    if (d < W) {
        const float* krow = base + (size_t)(klo + d) * THREE_D + DMODEL + h * HD;
        float s = 0.0f;
#pragma unroll
        for (int i = 0; i < HD; i++) s += sQ[i] * krow[i];
        sS[d] = s * 0.125f;   // 1/sqrt(64)
    }
    __syncthreads();

    // max (redundant across threads, W<=33)
    float m = -3.402823466e38f;
    for (int j = 0; j < W; j++) m = fmaxf(m, sS[j]);
    if (d < W) sP[d] = __expf(sS[d] - m);
    __syncthreads();

    float denom = 0.0f;
    for (int j = 0; j < W; j++) denom += sP[j];
    const float inv_denom = 1.0f / denom;

    // out_d = sum_j p_j * v[klo+j][d]
    float accv = 0.0f;
    const float* vbase = base + 2 * DMODEL + h * HD + d;
    for (int j = 0; j < W; j++)
        accv += sP[j] * vbase[(size_t)(klo + j) * THREE_D];

    out[((size_t)b * SEQT + q) * DMODEL + h * HD + d] = accv * inv_denom;
}

// ---------------------------------------------------------------------------
extern "C" void kernel_launch(void* const* d_in, const int* in_sizes, int n_in,
                              void* d_out, int out_size)
{
    const float* x      = (const float*)d_in[0];  // [B,T,D]
    const float* radius = (const float*)d_in[1];  // [H]
    const float* w_in   = (const float*)d_in[2];  // [3D, D]
    const float* b_in   = (const float*)d_in[3];  // [3D]
    const float* w_out  = (const float*)d_in[4];  // [D, D]
    const float* b_out  = (const float*)d_in[5];  // [D]
    float* out = (float*)d_out;                   // [B,T,D]

    float* qkv;
    float* att;
    cudaGetSymbolAddress((void**)&qkv, g_qkv);
    cudaGetSymbolAddress((void**)&att, g_att);

    // 1) QKV projection: [8192,512] x [1536,512]^T -> [8192,1536]
    {
        dim3 grid(THREE_D / 128, MROWS / 128);
        sgemm_bias_kernel<<<grid, 256>>>(x, w_in, b_in, qkv,
                                         MROWS, THREE_D, DMODEL);
    }

    // 2) Band attention -> att [8192, 512]
    {
        dim3 grid(SEQT, NHEAD, BATCH);
        band_attn_kernel<<<grid, 64>>>(radius, att);
    }

    // 3) Output projection: [8192,512] x [512,512]^T -> [8192,512]
    {
        dim3 grid(DMODEL / 128, MROWS / 128);
        sgemm_bias_kernel<<<grid, 256>>>(att, w_out, b_out, out,
                                         MROWS, DMODEL, DMODEL);
    }
}

// round 3
// speedup vs baseline: 1.9035x; 1.9035x over previous
#include <cuda_runtime.h>
#include <cuda_bf16.h>
#include <cstdint>

// Problem constants
#define BATCH 4
#define SEQT  2048
#define DMODEL 512
#define NHEAD 8
#define HD    64
#define THREE_D (3 * DMODEL)
#define MROWS (BATCH * SEQT)        // 8192
#define MAX_R 16
#define MAX_W (2 * MAX_R + 1)       // 33

// Arch-feature dispatch: tcgen05 only exists on *a targets.
// Host pass (__CUDA_ARCH__ undefined) keeps TC path for parsing only.
#if !defined(__CUDA_ARCH__)
#  define TC_PATH 1
#elif defined(__CUDA_ARCH_HAS_FEATURE__) && \
      (__CUDA_ARCH_HAS_FEATURE__(SM103_ALL) || __CUDA_ARCH_HAS_FEATURE__(SM100_ALL))
#  define TC_PATH 1
#else
#  define TC_PATH 0
#endif

// Scratch (no cudaMalloc allowed)
__device__ float g_qkv[(size_t)BATCH * SEQT * THREE_D];   // 48 MB
__device__ float g_att[(size_t)BATCH * SEQT * DMODEL];    // 16 MB

// ===========================================================================
// PTX helpers (only compiled into feature-enabled device passes)
// ===========================================================================
#if TC_PATH
__device__ __forceinline__ uint32_t smem_u32(const void* p) {
    uint32_t a;
    asm("{ .reg .u64 t; cvta.to.shared.u64 t, %1; cvt.u32.u64 %0, t; }"
        : "=r"(a) : "l"(p));
    return a;
}

__device__ __forceinline__ uint32_t elect_one_pred() {
    uint32_t pred;
    asm volatile(
        "{\n\t.reg .pred p;\n\t"
        "elect.sync _|p, 0xFFFFFFFF;\n\t"
        "selp.b32 %0, 1, 0, p;\n\t}"
        : "=r"(pred));
    return pred;
}

#define TCGEN05_ALLOC(smem_result_addr, nCols) \
    asm volatile( \
        "tcgen05.alloc.cta_group::1.sync.aligned.shared::cta.b32 [%0], %1;" \
        :: "r"((uint32_t)(smem_result_addr)), "r"((uint32_t)(nCols)) : "memory")

#define TCGEN05_DEALLOC(tmem_addr, nCols) \
    asm volatile( \
        "tcgen05.dealloc.cta_group::1.sync.aligned.b32 %0, %1;" \
        :: "r"(tmem_addr), "r"((uint32_t)(nCols)))

#define TCGEN05_RELINQUISH_ALLOC_PERMIT() \
    asm volatile("tcgen05.relinquish_alloc_permit.cta_group::1.sync.aligned;")

#define TCGEN05_COMMIT(mbar_smem_addr) \
    asm volatile( \
        "tcgen05.commit.cta_group::1.mbarrier::arrive::one.shared::cluster.b64 [%0];" \
        :: "r"((uint32_t)(mbar_smem_addr)) : "memory")

#define TCGEN05_FENCE_AFTER() \
    asm volatile("tcgen05.fence::after_thread_sync;" ::: "memory")

#define TCGEN05_WAIT_LD() \
    asm volatile("tcgen05.wait::ld.sync.aligned;" ::: "memory")

#define FENCE_PROXY_ASYNC_SHARED_CTA() \
    asm volatile("fence.proxy.async.shared::cta;" ::: "memory")

#define MBARRIER_INIT(mbar_smem_addr, count) \
    asm volatile( \
        "mbarrier.init.shared.b64 [%0], %1;" \
        :: "r"((uint32_t)(mbar_smem_addr)), "r"((uint32_t)(count)) : "memory")

#define MBARRIER_WAIT_PARITY(mbar_smem_addr, phase_parity) do { \
    uint32_t _mbar = (uint32_t)(mbar_smem_addr); \
    uint32_t _parity = (uint32_t)(phase_parity); \
    uint32_t _done; \
    asm volatile( \
        "{\n\t.reg .pred p;\n\t" \
        "mbarrier.try_wait.parity.acquire.cta.shared::cta.b64 p, [%1], %2;\n\t" \
        "selp.b32 %0, 1, 0, p;\n\t}" \
        : "=r"(_done) : "r"(_mbar), "r"(_parity) : "memory"); \
    if (!_done) { \
        asm volatile( \
            "{\n\t.reg .pred P1;\n\t" \
            "WAIT_LOOP_%=:\n\t" \
            "mbarrier.try_wait.parity.acquire.cta.shared::cta.b64 P1, [%0], %1, 0x989680;\n\t" \
            "@P1 bra.uni WAIT_DONE_%=;\n\t" \
            "bra.uni WAIT_LOOP_%=;\n\t" \
            "WAIT_DONE_%=:\n\t}" \
            :: "r"(_mbar), "r"(_parity) : "memory"); \
    } \
} while(0)

#define TCGEN05_LD_32X32B_X32(r, tmem_addr) \
    asm volatile( \
        "tcgen05.ld.sync.aligned.32x32b.x32.b32 " \
        "{%0, %1, %2, %3, %4, %5, %6, %7, " \
        " %8, %9, %10, %11, %12, %13, %14, %15, " \
        " %16, %17, %18, %19, %20, %21, %22, %23, " \
        " %24, %25, %26, %27, %28, %29, %30, %31}, [%32];" \
        : "=r"((r)[0]),  "=r"((r)[1]),  "=r"((r)[2]),  "=r"((r)[3]), \
          "=r"((r)[4]),  "=r"((r)[5]),  "=r"((r)[6]),  "=r"((r)[7]), \
          "=r"((r)[8]),  "=r"((r)[9]),  "=r"((r)[10]), "=r"((r)[11]), \
          "=r"((r)[12]), "=r"((r)[13]), "=r"((r)[14]), "=r"((r)[15]), \
          "=r"((r)[16]), "=r"((r)[17]), "=r"((r)[18]), "=r"((r)[19]), \
          "=r"((r)[20]), "=r"((r)[21]), "=r"((r)[22]), "=r"((r)[23]), \
          "=r"((r)[24]), "=r"((r)[25]), "=r"((r)[26]), "=r"((r)[27]), \
          "=r"((r)[28]), "=r"((r)[29]), "=r"((r)[30]), "=r"((r)[31]) \
        : "r"(tmem_addr))

// SMEM descriptor: SW128, version=1, SBO=64, LBO=1 (K-major, 128B rows)
static constexpr uint64_t SMEM_DESC_BASE_SW128 =
    (uint64_t(2)  << 61) | (uint64_t(1) << 46) |
    (uint64_t(64) << 32) | (uint64_t(1) << 16);
#define MAKE_SMEM_DESC(base_addr) \
    (SMEM_DESC_BASE_SW128 | ((uint64_t)((base_addr) >> 4) & 0x3FFF))

// SS-mode cg1 bf16 MMA (kind::f16)
__device__ __forceinline__ void mma_f16_ss_cg1(
    uint32_t d_tmem, uint64_t a_desc, uint64_t b_desc,
    uint32_t idesc, uint32_t enable)
{
    asm volatile(
        "{\n\t.reg .pred p;\n\t"
        "setp.ne.u32 p, %4, 0;\n\t"
        "tcgen05.mma.cta_group::1.kind::f16 [%0], %1, %2, %3, "
        "{%5, %5, %5, %5}, p;\n\t}"
        :: "r"(d_tmem), "l"(a_desc), "l"(b_desc), "r"(idesc),
           "r"(enable), "r"(0u)
        : "memory");
}

#define GEMM_IDESC ((1u<<4)|(1u<<7)|(1u<<10)|(16u<<17)|(8u<<24))

__device__ __forceinline__ uint32_t pack_bf16x2(__nv_bfloat16 a, __nv_bfloat16 b) {
    return (uint32_t)__bfloat16_as_ushort(a) |
           ((uint32_t)__bfloat16_as_ushort(b) << 16);
}

__device__ __forceinline__ void cvt_hilo4(float4 v, uint2& hi, uint2& lo) {
    __nv_bfloat16 hx = __float2bfloat16(v.x);
    __nv_bfloat16 hy = __float2bfloat16(v.y);
    __nv_bfloat16 hz = __float2bfloat16(v.z);
    __nv_bfloat16 hw = __float2bfloat16(v.w);
    __nv_bfloat16 lx = __float2bfloat16(v.x - __bfloat162float(hx));
    __nv_bfloat16 ly = __float2bfloat16(v.y - __bfloat162float(hy));
    __nv_bfloat16 lz = __float2bfloat16(v.z - __bfloat162float(hz));
    __nv_bfloat16 lw = __float2bfloat16(v.w - __bfloat162float(hw));
    hi.x = pack_bf16x2(hx, hy); hi.y = pack_bf16x2(hz, hw);
    lo.x = pack_bf16x2(lx, ly); lo.y = pack_bf16x2(lz, lw);
}
#endif // TC_PATH

// dynamic smem: header(1KB) + Ah,Al,Bh,Bl (4 x 16KB)
#define GEMM_SMEM_TOTAL (1024 + 4 * 16384)

// ===========================================================================
// GEMM: C[M,N] = A[M,K] @ B[N,K]^T + bias[N]   (fp32 in/out)
//   feature path: tcgen05 bf16 hi/lo split (3 accumulating MMAs / K-step)
//   fallback    : 128x128 FFMA SGEMM (R1, known-correct)
// Grid (N/128, M/128), 256 threads, GEMM_SMEM_TOTAL dynamic smem.
// ===========================================================================
__global__ __launch_bounds__(256) void gemm_bias_kernel(
    const float* __restrict__ A, const float* __restrict__ B,
    const float* __restrict__ bias, float* __restrict__ C,
    int M, int N, int K)
{
    extern __shared__ char smem[];
    const int tid  = threadIdx.x;
    const int bm = blockIdx.y * 128;
    const int bn = blockIdx.x * 128;

#if TC_PATH
    // ---------------- tcgen05 path ----------------
    const uint32_t smem_base = smem_u32(smem);
    const int wid  = tid >> 5;
    const int lane = tid & 31;

    const uint32_t OFF_MBAR = 8;
    const uint32_t OFF_AH = 1024;
    const uint32_t OFF_AL = 1024 + 16384;
    const uint32_t OFF_BH = 1024 + 32768;
    const uint32_t OFF_BL = 1024 + 49152;

    if (wid == 0) {
        TCGEN05_ALLOC(smem_base, 128);
        if (lane == 0) MBARRIER_INIT(smem_base + OFF_MBAR, 1);
    }
    __syncthreads();
    uint32_t tmem;
    asm volatile("ld.shared.b32 %0, [%1];" : "=r"(tmem) : "r"(smem_base));

    const int nstage = K >> 6;

    for (int s = 0; s < nstage; s++) {
        const int k0 = s << 6;

        float4 av[8], bv[8];
#pragma unroll
        for (int i = 0; i < 8; i++) {
            int idx = i * 256 + tid;
            int r   = idx >> 4;
            int c4  = idx & 15;
            av[i] = __ldg((const float4*)(A + (size_t)(bm + r) * K + k0 + c4 * 4));
            bv[i] = __ldg((const float4*)(B + (size_t)(bn + r) * K + k0 + c4 * 4));
        }

        if (s > 0) MBARRIER_WAIT_PARITY(smem_base + OFF_MBAR, (s - 1) & 1);

#pragma unroll
        for (int i = 0; i < 8; i++) {
            int idx = i * 256 + tid;
            int r   = idx >> 4;
            int c4  = idx & 15;
            uint32_t bo = (uint32_t)(r * 128 + c4 * 8);
            uint32_t so = bo ^ ((bo >> 3) & 0x70);
            uint2 ahi, alo, bhi, blo;
            cvt_hilo4(av[i], ahi, alo);
            cvt_hilo4(bv[i], bhi, blo);
            *(uint2*)(smem + OFF_AH + so) = ahi;
            *(uint2*)(smem + OFF_AL + so) = alo;
            *(uint2*)(smem + OFF_BH + so) = bhi;
            *(uint2*)(smem + OFF_BL + so) = blo;
        }
        FENCE_PROXY_ASYNC_SHARED_CTA();
        __syncthreads();

        if (wid == 0) {
            if (elect_one_pred()) {
                uint64_t ah = MAKE_SMEM_DESC(smem_base + OFF_AH);
                uint64_t al = MAKE_SMEM_DESC(smem_base + OFF_AL);
                uint64_t bh = MAKE_SMEM_DESC(smem_base + OFF_BH);
                uint64_t bl = MAKE_SMEM_DESC(smem_base + OFF_BL);
#pragma unroll
                for (int kk = 0; kk < 4; kk++) {
                    uint32_t en0 = (s > 0 || kk > 0) ? 1u : 0u;
                    mma_f16_ss_cg1(tmem, ah + kk * 2, bh + kk * 2, GEMM_IDESC, en0);
                    mma_f16_ss_cg1(tmem, ah + kk * 2, bl + kk * 2, GEMM_IDESC, 1u);
                    mma_f16_ss_cg1(tmem, al + kk * 2, bh + kk * 2, GEMM_IDESC, 1u);
                }
                TCGEN05_COMMIT(smem_base + OFF_MBAR);
            }
        }
    }

    MBARRIER_WAIT_PARITY(smem_base + OFF_MBAR, (nstage - 1) & 1);
    TCGEN05_FENCE_AFTER();

    if (wid < 4) {
        const int rowo = bm + wid * 32 + lane;
#pragma unroll
        for (int cb = 0; cb < 128; cb += 32) {
            uint32_t d[32];
            TCGEN05_LD_32X32B_X32(d, tmem + cb);
            TCGEN05_WAIT_LD();
            float* crow = C + (size_t)rowo * N + bn + cb;
#pragma unroll
            for (int g = 0; g < 8; g++) {
                float4 bb = __ldg((const float4*)(bias + bn + cb + g * 4));
                float4 o;
                o.x = __uint_as_float(d[g*4+0]) + bb.x;
                o.y = __uint_as_float(d[g*4+1]) + bb.y;
                o.z = __uint_as_float(d[g*4+2]) + bb.z;
                o.w = __uint_as_float(d[g*4+3]) + bb.w;
                *(float4*)(crow + g * 4) = o;
            }
        }
    }
    __syncthreads();
    if (wid == 0) {
        TCGEN05_RELINQUISH_ALLOC_PERMIT();
        TCGEN05_DEALLOC(tmem, 128);
    }

#else
    // ---------------- FFMA fallback (R1 SGEMM) ----------------
    float* As = (float*)smem;            // [8][128]
    float* Bs = (float*)(smem + 4096);   // [8][128]

    const int trow = tid >> 4;
    const int tcol = tid & 15;
    const int lrow = tid >> 1;
    const int lk4  = (tid & 1) << 2;

    const float* Aptr = A + (size_t)(bm + lrow) * K + lk4;
    const float* Bptr = B + (size_t)(bn + lrow) * K + lk4;

    float acc[8][8];
#pragma unroll
    for (int i = 0; i < 8; i++)
#pragma unroll
        for (int j = 0; j < 8; j++) acc[i][j] = 0.0f;

    for (int k0 = 0; k0 < K; k0 += 8) {
        float4 avv = *(const float4*)(Aptr + k0);
        float4 bvv = *(const float4*)(Bptr + k0);

        As[(lk4 + 0) * 128 + lrow] = avv.x;
        As[(lk4 + 1) * 128 + lrow] = avv.y;
        As[(lk4 + 2) * 128 + lrow] = avv.z;
        As[(lk4 + 3) * 128 + lrow] = avv.w;
        Bs[(lk4 + 0) * 128 + lrow] = bvv.x;
        Bs[(lk4 + 1) * 128 + lrow] = bvv.y;
        Bs[(lk4 + 2) * 128 + lrow] = bvv.z;
        Bs[(lk4 + 3) * 128 + lrow] = bvv.w;
        __syncthreads();

#pragma unroll
        for (int kk = 0; kk < 8; kk++) {
            float a[8], b[8];
            float4 a0 = *(const float4*)&As[kk * 128 + trow * 8];
            float4 a1 = *(const float4*)&As[kk * 128 + trow * 8 + 4];
            float4 b0 = *(const float4*)&Bs[kk * 128 + tcol * 8];
            float4 b1 = *(const float4*)&Bs[kk * 128 + tcol * 8 + 4];
            a[0]=a0.x; a[1]=a0.y; a[2]=a0.z; a[3]=a0.w;
            a[4]=a1.x; a[5]=a1.y; a[6]=a1.z; a[7]=a1.w;
            b[0]=b0.x; b[1]=b0.y; b[2]=b0.z; b[3]=b0.w;
            b[4]=b1.x; b[5]=b1.y; b[6]=b1.z; b[7]=b1.w;
#pragma unroll
            for (int i = 0; i < 8; i++)
#pragma unroll
                for (int j = 0; j < 8; j++)
                    acc[i][j] += a[i] * b[j];
        }
        __syncthreads();
    }

    const int cn = bn + tcol * 8;
    float4 bias0 = *(const float4*)(bias + cn);
    float4 bias1 = *(const float4*)(bias + cn + 4);
#pragma unroll
    for (int i = 0; i < 8; i++) {
        const int row = bm + trow * 8 + i;
        float4 o0, o1;
        o0.x = acc[i][0] + bias0.x; o0.y = acc[i][1] + bias0.y;
        o0.z = acc[i][2] + bias0.z; o0.w = acc[i][3] + bias0.w;
        o1.x = acc[i][4] + bias1.x; o1.y = acc[i][5] + bias1.y;
        o1.z = acc[i][6] + bias1.z; o1.w = acc[i][7] + bias1.w;
        *(float4*)(C + (size_t)row * N + cn)     = o0;
        *(float4*)(C + (size_t)row * N + cn + 4) = o1;
    }
#endif
}

// ---------------------------------------------------------------------------
// Band attention (unchanged — known correct)
// ---------------------------------------------------------------------------
__global__ __launch_bounds__(64) void band_attn_kernel(
    const float* __restrict__ radius, float* __restrict__ out)
{
    const int q = blockIdx.x;
    const int h = blockIdx.y;
    const int b = blockIdx.z;
    const int d = threadIdx.x;

    float rr = 16.0f / (1.0f + expf(-radius[h]));
    if (rr < 1.0f) rr = 1.0f;
    const int R = (int)floorf(rr);

    int klo = q - R; if (klo < 0) klo = 0;
    int khi = q + R; if (khi > SEQT - 1) khi = SEQT - 1;
    const int W = khi - klo + 1;

    const float* base = g_qkv + (size_t)b * SEQT * THREE_D;
    const float* qrow = base + (size_t)q * THREE_D + h * HD;

    __shared__ float sQ[HD];
    __shared__ float sP[MAX_W];
    __shared__ float sS[MAX_W];

    sQ[d] = qrow[d];
    __syncthreads();

    if (d < W) {
        const float* krow = base + (size_t)(klo + d) * THREE_D + DMODEL + h * HD;
        float s = 0.0f;
#pragma unroll
        for (int i = 0; i < HD; i++) s += sQ[i] * krow[i];
        sS[d] = s * 0.125f;
    }
    __syncthreads();

    float m = -3.402823466e38f;
    for (int j = 0; j < W; j++) m = fmaxf(m, sS[j]);
    if (d < W) sP[d] = __expf(sS[d] - m);
    __syncthreads();

    float denom = 0.0f;
    for (int j = 0; j < W; j++) denom += sP[j];
    const float inv_denom = 1.0f / denom;

    float accv = 0.0f;
    const float* vbase = base + 2 * DMODEL + h * HD + d;
    for (int j = 0; j < W; j++)
        accv += sP[j] * vbase[(size_t)(klo + j) * THREE_D];

    out[((size_t)b * SEQT + q) * DMODEL + h * HD + d] = accv * inv_denom;
}

// ---------------------------------------------------------------------------
extern "C" void kernel_launch(void* const* d_in, const int* in_sizes, int n_in,
                              void* d_out, int out_size)
{
    const float* x      = (const float*)d_in[0];
    const float* radius = (const float*)d_in[1];
    const float* w_in   = (const float*)d_in[2];
    const float* b_in   = (const float*)d_in[3];
    const float* w_out  = (const float*)d_in[4];
    const float* b_out  = (const float*)d_in[5];
    float* out = (float*)d_out;

    float* qkv;
    float* att;
    cudaGetSymbolAddress((void**)&qkv, g_qkv);
    cudaGetSymbolAddress((void**)&att, g_att);

    cudaFuncSetAttribute(gemm_bias_kernel,
                         cudaFuncAttributeMaxDynamicSharedMemorySize,
                         GEMM_SMEM_TOTAL);

    // 1) QKV projection
    {
        dim3 grid(THREE_D / 128, MROWS / 128);
        gemm_bias_kernel<<<grid, 256, GEMM_SMEM_TOTAL>>>(
            x, w_in, b_in, qkv, MROWS, THREE_D, DMODEL);
    }

    // 2) Band attention
    {
        dim3 grid(SEQT, NHEAD, BATCH);
        band_attn_kernel<<<grid, 64>>>(radius, att);
    }

    // 3) Output projection
    {
        dim3 grid(DMODEL / 128, MROWS / 128);
        gemm_bias_kernel<<<grid, 256, GEMM_SMEM_TOTAL>>>(
            att, w_out, b_out, out, MROWS, DMODEL, DMODEL);
    }
}

// round 4
// speedup vs baseline: 3.6645x; 1.9252x over previous
#include <cuda_runtime.h>
#include <cuda_bf16.h>
#include <cstdint>

// Problem constants
#define BATCH 4
#define SEQT  2048
#define DMODEL 512
#define NHEAD 8
#define HD    64
#define THREE_D (3 * DMODEL)
#define MROWS (BATCH * SEQT)        // 8192

// Arch-feature dispatch: tcgen05 only exists on *a targets.
#if !defined(__CUDA_ARCH__)
#  define TC_PATH 1
#elif defined(__CUDA_ARCH_HAS_FEATURE__) && \
      (__CUDA_ARCH_HAS_FEATURE__(SM103_ALL) || __CUDA_ARCH_HAS_FEATURE__(SM100_ALL))
#  define TC_PATH 1
#else
#  define TC_PATH 0
#endif

// Scratch (no cudaMalloc allowed)
__device__ float         g_qkv[(size_t)MROWS * THREE_D];   // 48 MB fp32
__device__ __nv_bfloat16 g_xh[(size_t)MROWS * DMODEL];
__device__ __nv_bfloat16 g_xl[(size_t)MROWS * DMODEL];
__device__ __nv_bfloat16 g_wih[(size_t)THREE_D * DMODEL];
__device__ __nv_bfloat16 g_wil[(size_t)THREE_D * DMODEL];
__device__ __nv_bfloat16 g_woh[(size_t)DMODEL * DMODEL];
__device__ __nv_bfloat16 g_wol[(size_t)DMODEL * DMODEL];
__device__ __nv_bfloat16 g_atth[(size_t)MROWS * DMODEL];
__device__ __nv_bfloat16 g_attl[(size_t)MROWS * DMODEL];

// ===========================================================================
// Common helpers (no tcgen05 — compile everywhere)
// ===========================================================================
__device__ __forceinline__ uint32_t pack_bf16x2(__nv_bfloat16 a, __nv_bfloat16 b) {
    return (uint32_t)__bfloat16_as_ushort(a) |
           ((uint32_t)__bfloat16_as_ushort(b) << 16);
}

__device__ __forceinline__ void split_hilo(float v, __nv_bfloat16& h, __nv_bfloat16& l) {
    h = __float2bfloat16(v);
    l = __float2bfloat16(v - __bfloat162float(h));
}

// ===========================================================================
// fp32 -> bf16 hi/lo convert kernel (grid-stride over float4)
// ===========================================================================
__global__ __launch_bounds__(256) void cvt_hilo_kernel(
    const float* __restrict__ src,
    __nv_bfloat16* __restrict__ dh, __nv_bfloat16* __restrict__ dl, int n4)
{
    int i = blockIdx.x * blockDim.x + threadIdx.x;
    if (i >= n4) return;
    float4 v = __ldg((const float4*)src + i);
    __nv_bfloat16 hx, lx, hy, ly, hz, lz, hw, lw;
    split_hilo(v.x, hx, lx); split_hilo(v.y, hy, ly);
    split_hilo(v.z, hz, lz); split_hilo(v.w, hw, lw);
    uint2 ho, lo;
    ho.x = pack_bf16x2(hx, hy); ho.y = pack_bf16x2(hz, hw);
    lo.x = pack_bf16x2(lx, ly); lo.y = pack_bf16x2(lz, lw);
    ((uint2*)dh)[i] = ho;
    ((uint2*)dl)[i] = lo;
}

// ===========================================================================
// tcgen05 PTX helpers (feature-gated)
// ===========================================================================
#if TC_PATH
__device__ __forceinline__ uint32_t smem_u32(const void* p) {
    uint32_t a;
    asm("{ .reg .u64 t; cvta.to.shared.u64 t, %1; cvt.u32.u64 %0, t; }"
        : "=r"(a) : "l"(p));
    return a;
}

__device__ __forceinline__ uint32_t elect_one_pred() {
    uint32_t pred;
    asm volatile(
        "{\n\t.reg .pred p;\n\t"
        "elect.sync _|p, 0xFFFFFFFF;\n\t"
        "selp.b32 %0, 1, 0, p;\n\t}"
        : "=r"(pred));
    return pred;
}

#define TCGEN05_ALLOC(smem_result_addr, nCols) \
    asm volatile( \
        "tcgen05.alloc.cta_group::1.sync.aligned.shared::cta.b32 [%0], %1;" \
        :: "r"((uint32_t)(smem_result_addr)), "r"((uint32_t)(nCols)) : "memory")

#define TCGEN05_DEALLOC(tmem_addr, nCols) \
    asm volatile( \
        "tcgen05.dealloc.cta_group::1.sync.aligned.b32 %0, %1;" \
        :: "r"(tmem_addr), "r"((uint32_t)(nCols)))

#define TCGEN05_RELINQUISH_ALLOC_PERMIT() \
    asm volatile("tcgen05.relinquish_alloc_permit.cta_group::1.sync.aligned;")

#define TCGEN05_COMMIT(mbar_smem_addr) \
    asm volatile( \
        "tcgen05.commit.cta_group::1.mbarrier::arrive::one.shared::cluster.b64 [%0];" \
        :: "r"((uint32_t)(mbar_smem_addr)) : "memory")

#define TCGEN05_FENCE_AFTER() \
    asm volatile("tcgen05.fence::after_thread_sync;" ::: "memory")

#define TCGEN05_WAIT_LD() \
    asm volatile("tcgen05.wait::ld.sync.aligned;" ::: "memory")

#define FENCE_PROXY_ASYNC_SHARED_CTA() \
    asm volatile("fence.proxy.async.shared::cta;" ::: "memory")

#define MBARRIER_INIT(mbar_smem_addr, count) \
    asm volatile( \
        "mbarrier.init.shared.b64 [%0], %1;" \
        :: "r"((uint32_t)(mbar_smem_addr)), "r"((uint32_t)(count)) : "memory")

#define MBARRIER_WAIT_PARITY(mbar_smem_addr, phase_parity) do { \
    uint32_t _mbar = (uint32_t)(mbar_smem_addr); \
    uint32_t _parity = (uint32_t)(phase_parity); \
    uint32_t _done; \
    asm volatile( \
        "{\n\t.reg .pred p;\n\t" \
        "mbarrier.try_wait.parity.acquire.cta.shared::cta.b64 p, [%1], %2;\n\t" \
        "selp.b32 %0, 1, 0, p;\n\t}" \
        : "=r"(_done) : "r"(_mbar), "r"(_parity) : "memory"); \
    if (!_done) { \
        asm volatile( \
            "{\n\t.reg .pred P1;\n\t" \
            "WAIT_LOOP_%=:\n\t" \
            "mbarrier.try_wait.parity.acquire.cta.shared::cta.b64 P1, [%0], %1, 0x989680;\n\t" \
            "@P1 bra.uni WAIT_DONE_%=;\n\t" \
            "bra.uni WAIT_LOOP_%=;\n\t" \
            "WAIT_DONE_%=:\n\t}" \
            :: "r"(_mbar), "r"(_parity) : "memory"); \
    } \
} while(0)

#define TCGEN05_LD_32X32B_X32(r, tmem_addr) \
    asm volatile( \
        "tcgen05.ld.sync.aligned.32x32b.x32.b32 " \
        "{%0, %1, %2, %3, %4, %5, %6, %7, " \
        " %8, %9, %10, %11, %12, %13, %14, %15, " \
        " %16, %17, %18, %19, %20, %21, %22, %23, " \
        " %24, %25, %26, %27, %28, %29, %30, %31}, [%32];" \
        : "=r"((r)[0]),  "=r"((r)[1]),  "=r"((r)[2]),  "=r"((r)[3]), \
          "=r"((r)[4]),  "=r"((r)[5]),  "=r"((r)[6]),  "=r"((r)[7]), \
          "=r"((r)[8]),  "=r"((r)[9]),  "=r"((r)[10]), "=r"((r)[11]), \
          "=r"((r)[12]), "=r"((r)[13]), "=r"((r)[14]), "=r"((r)[15]), \
          "=r"((r)[16]), "=r"((r)[17]), "=r"((r)[18]), "=r"((r)[19]), \
          "=r"((r)[20]), "=r"((r)[21]), "=r"((r)[22]), "=r"((r)[23]), \
          "=r"((r)[24]), "=r"((r)[25]), "=r"((r)[26]), "=r"((r)[27]), \
          "=r"((r)[28]), "=r"((r)[29]), "=r"((r)[30]), "=r"((r)[31]) \
        : "r"(tmem_addr))

static constexpr uint64_t SMEM_DESC_BASE_SW128 =
    (uint64_t(2)  << 61) | (uint64_t(1) << 46) |
    (uint64_t(64) << 32) | (uint64_t(1) << 16);
#define MAKE_SMEM_DESC(base_addr) \
    (SMEM_DESC_BASE_SW128 | ((uint64_t)((base_addr) >> 4) & 0x3FFF))

__device__ __forceinline__ void mma_f16_ss_cg1(
    uint32_t d_tmem, uint64_t a_desc, uint64_t b_desc,
    uint32_t idesc, uint32_t enable)
{
    asm volatile(
        "{\n\t.reg .pred p;\n\t"
        "setp.ne.u32 p, %4, 0;\n\t"
        "tcgen05.mma.cta_group::1.kind::f16 [%0], %1, %2, %3, "
        "{%5, %5, %5, %5}, p;\n\t}"
        :: "r"(d_tmem), "l"(a_desc), "l"(b_desc), "r"(idesc),
           "r"(enable), "r"(0u)
        : "memory");
}

#define GEMM_IDESC ((1u<<4)|(1u<<7)|(1u<<10)|(16u<<17)|(8u<<24))
#endif // TC_PATH

// dynamic smem: header(1KB) + 2 buffers x (Ah,Al,Bh,Bl each 16KB)
#define GEMM_SMEM_TOTAL (1024 + 2 * 4 * 16384)

// ===========================================================================
// GEMM: C[M,N] = (Ah+Al)[M,K] @ (Bh+Bl)[N,K]^T + bias[N]
// Inputs pre-split bf16 hi/lo. Tile 128x128, K-chunk 64, double-buffered.
// Grid (N/128, M/128), 256 threads. K%128==0 (>=2 even stages).
// ===========================================================================
__global__ __launch_bounds__(256) void tc_gemm_bf16(
    const __nv_bfloat16* __restrict__ Ah, const __nv_bfloat16* __restrict__ Al,
    const __nv_bfloat16* __restrict__ Bh, const __nv_bfloat16* __restrict__ Bl,
    const float* __restrict__ bias, float* __restrict__ C,
    int M, int N, int K)
{
    extern __shared__ char smem[];
    const int tid  = threadIdx.x;
    const int bm = blockIdx.y * 128;
    const int bn = blockIdx.x * 128;

#if TC_PATH
    const uint32_t smem_base = smem_u32(smem);
    const int wid  = tid >> 5;
    const int lane = tid & 31;

    const uint32_t OFF_MB0 = 8;
    const uint32_t OFF_MB1 = 16;

    if (wid == 0) {
        TCGEN05_ALLOC(smem_base, 128);
        if (lane == 0) {
            MBARRIER_INIT(smem_base + OFF_MB0, 1);
            MBARRIER_INIT(smem_base + OFF_MB1, 1);
        }
    }
    __syncthreads();
    uint32_t tmem;
    asm volatile("ld.shared.b32 %0, [%1];" : "=r"(tmem) : "r"(smem_base));

    const int nstage = K >> 6;
    int ph0 = 0, ph1 = 0;

    // per-thread load mapping: 4 x uint4 per array per stage
    const int r_of[4]  = { (tid*16) >> 7, (256*16 + tid*16) >> 7,
                           (512*16 + tid*16) >> 7, (768*16 + tid*16) >> 7 };
    // cbyte per chunk: bo & 127
    for (int s = 0; s < nstage; s++) {
        const int buf = s & 1;
        const uint32_t OFF = 1024 + buf * 65536;
        const int k0 = s << 6;

        // global loads first (don't touch smem)
        uint4 va[4], vl[4], wb[4], wl[4];
#pragma unroll
        for (int i = 0; i < 4; i++) {
            uint32_t bo = (uint32_t)((i * 256 + tid) * 16);
            int r = bo >> 7;
            int cbyte = bo & 127;
            size_t abyte = ((size_t)(bm + r) * K + k0) * 2 + cbyte;
            size_t bbyte = ((size_t)(bn + r) * K + k0) * 2 + cbyte;
            va[i] = __ldg((const uint4*)((const char*)Ah + abyte));
            vl[i] = __ldg((const uint4*)((const char*)Al + abyte));
            wb[i] = __ldg((const uint4*)((const char*)Bh + bbyte));
            wl[i] = __ldg((const uint4*)((const char*)Bl + bbyte));
        }

        // ensure this buffer's previous MMAs finished
        if (s >= 2) {
            if (buf == 0) { MBARRIER_WAIT_PARITY(smem_base + OFF_MB0, ph0); ph0 ^= 1; }
            else          { MBARRIER_WAIT_PARITY(smem_base + OFF_MB1, ph1); ph1 ^= 1; }
        }

#pragma unroll
        for (int i = 0; i < 4; i++) {
            uint32_t bo = (uint32_t)((i * 256 + tid) * 16);
            uint32_t so = bo ^ ((bo >> 3) & 0x70);
            *(uint4*)(smem + OFF +         so) = va[i];
            *(uint4*)(smem + OFF + 16384 + so) = vl[i];
            *(uint4*)(smem + OFF + 32768 + so) = wb[i];
            *(uint4*)(smem + OFF + 49152 + so) = wl[i];
        }
        FENCE_PROXY_ASYNC_SHARED_CTA();
        __syncthreads();

        if (wid == 0) {
            if (elect_one_pred()) {
                uint64_t ah = MAKE_SMEM_DESC(smem_base + OFF);
                uint64_t al = MAKE_SMEM_DESC(smem_base + OFF + 16384);
                uint64_t bh = MAKE_SMEM_DESC(smem_base + OFF + 32768);
                uint64_t bl = MAKE_SMEM_DESC(smem_base + OFF + 49152);
#pragma unroll
                for (int kk = 0; kk < 4; kk++) {
                    uint32_t en0 = (s > 0 || kk > 0) ? 1u : 0u;
                    mma_f16_ss_cg1(tmem, ah + kk * 2, bh + kk * 2, GEMM_IDESC, en0);
                    mma_f16_ss_cg1(tmem, ah + kk * 2, bl + kk * 2, GEMM_IDESC, 1u);
                    mma_f16_ss_cg1(tmem, al + kk * 2, bh + kk * 2, GEMM_IDESC, 1u);
                }
                TCGEN05_COMMIT(smem_base + (buf == 0 ? OFF_MB0 : OFF_MB1));
            }
        }
    }

    // drain both buffers' outstanding commits
    MBARRIER_WAIT_PARITY(smem_base + OFF_MB0, ph0);
    MBARRIER_WAIT_PARITY(smem_base + OFF_MB1, ph1);
    TCGEN05_FENCE_AFTER();

    if (wid < 4) {
        const int rowo = bm + wid * 32 + lane;
#pragma unroll
        for (int cb = 0; cb < 128; cb += 32) {
            uint32_t d[32];
            TCGEN05_LD_32X32B_X32(d, tmem + cb);
            TCGEN05_WAIT_LD();
            float* crow = C + (size_t)rowo * N + bn + cb;
#pragma unroll
            for (int g = 0; g < 8; g++) {
                float4 bb = __ldg((const float4*)(bias + bn + cb + g * 4));
                float4 o;
                o.x = __uint_as_float(d[g*4+0]) + bb.x;
                o.y = __uint_as_float(d[g*4+1]) + bb.y;
                o.z = __uint_as_float(d[g*4+2]) + bb.z;
                o.w = __uint_as_float(d[g*4+3]) + bb.w;
                *(float4*)(crow + g * 4) = o;
            }
        }
    }
    __syncthreads();
    if (wid == 0) {
        TCGEN05_RELINQUISH_ALLOC_PERMIT();
        TCGEN05_DEALLOC(tmem, 128);
    }
    (void)r_of;

#else
    // ---------------- FFMA fallback (compiles everywhere; reconstructs fp32) ----
    float* As = (float*)smem;            // [8][128]
    float* Bs = (float*)(smem + 4096);

    const int trow = tid >> 4;
    const int tcol = tid & 15;
    const int lrow = tid >> 1;
    const int lk4  = (tid & 1) << 2;

    float acc[8][8];
#pragma unroll
    for (int i = 0; i < 8; i++)
#pragma unroll
        for (int j = 0; j < 8; j++) acc[i][j] = 0.0f;

    for (int k0 = 0; k0 < K; k0 += 8) {
        size_t abase = (size_t)(bm + lrow) * K + k0 + lk4;
        size_t bbase = (size_t)(bn + lrow) * K + k0 + lk4;
#pragma unroll
        for (int e = 0; e < 4; e++) {
            As[(lk4 + e) * 128 + lrow] =
                __bfloat162float(Ah[abase + e]) + __bfloat162float(Al[abase + e]);
            Bs[(lk4 + e) * 128 + lrow] =
                __bfloat162float(Bh[bbase + e]) + __bfloat162float(Bl[bbase + e]);
        }
        __syncthreads();
#pragma unroll
        for (int kk = 0; kk < 8; kk++) {
            float a[8], b[8];
#pragma unroll
            for (int e = 0; e < 8; e++) {
                a[e] = As[kk * 128 + trow * 8 + e];
                b[e] = Bs[kk * 128 + tcol * 8 + e];
            }
#pragma unroll
            for (int i = 0; i < 8; i++)
#pragma unroll
                for (int j = 0; j < 8; j++)
                    acc[i][j] += a[i] * b[j];
        }
        __syncthreads();
    }

    const int cn = bn + tcol * 8;
#pragma unroll
    for (int i = 0; i < 8; i++) {
        const int row = bm + trow * 8 + i;
#pragma unroll
        for (int j = 0; j < 8; j++)
            C[(size_t)row * N + cn + j] = acc[i][j] + bias[cn + j];
    }
#endif
}

// ===========================================================================
// Band attention: block = 64 queries x (h,b), 256 threads.
// Thread owns 2 adjacent queries x 8 dims. K/V tile in SMEM (<=96 rows).
// Scores: 8-lane shfl butterflies. Softmax+PV in registers.
// Writes att as bf16 hi/lo.
// ===========================================================================
#define ATT_ROWPAD 68
#define ATT_SMEM (2 * 96 * ATT_ROWPAD * 4)

__global__ __launch_bounds__(256) void band_attn_kernel(
    const float* __restrict__ qkv, const float* __restrict__ radius,
    __nv_bfloat16* __restrict__ atth, __nv_bfloat16* __restrict__ attl)
{
    extern __shared__ float sm[];
    float* sK = sm;
    float* sV = sm + 96 * ATT_ROWPAD;

    const int tid = threadIdx.x;
    const int q0 = blockIdx.x * 64;
    const int h  = blockIdx.y;
    const int b  = blockIdx.z;

    float rr = 16.0f / (1.0f + expf(-radius[h]));
    if (rr < 1.0f) rr = 1.0f;
    const int R = (int)floorf(rr);

    const int klo = max(0, q0 - R);
    const int khi = min(SEQT - 1, q0 + 63 + R);
    const int Wt  = khi - klo + 1;   // <= 96

    const float* base = qkv + (size_t)b * SEQT * THREE_D;

    // load K/V tile (coalesced float4)
    for (int i = tid; i < Wt * 16; i += 256) {
        int row = i >> 4;
        int c4  = (i & 15) * 4;
        const float* kr = base + (size_t)(klo + row) * THREE_D + DMODEL + h * HD + c4;
        *(float4*)&sK[row * ATT_ROWPAD + c4] = __ldg((const float4*)kr);
        *(float4*)&sV[row * ATT_ROWPAD + c4] = __ldg((const float4*)(kr + DMODEL));
    }

    const int pair  = tid >> 3;          // 0..31
    const int lane8 = tid & 7;           // d-group
    const int qA = q0 + pair * 2;
    const int qB = qA + 1;

    // Q fragments (8 dims each) straight from global
    float qFA[8], qFB[8];
    {
        const float* qa = base + (size_t)qA * THREE_D + h * HD + lane8 * 8;
        const float* qb = base + (size_t)qB * THREE_D + h * HD + lane8 * 8;
        float4 a0 = __ldg((const float4*)qa), a1 = __ldg((const float4*)(qa + 4));
        float4 b0 = __ldg((const float4*)qb), b1 = __ldg((const float4*)(qb + 4));
        qFA[0]=a0.x; qFA[1]=a0.y; qFA[2]=a0.z; qFA[3]=a0.w;
        qFA[4]=a1.x; qFA[5]=a1.y; qFA[6]=a1.z; qFA[7]=a1.w;
        qFB[0]=b0.x; qFB[1]=b0.y; qFB[2]=b0.z; qFB[3]=b0.w;
        qFB[4]=b1.x; qFB[5]=b1.y; qFB[6]=b1.z; qFB[7]=b1.w;
    }

    const int kAs = max(0, qA - R), kAe = min(SEQT - 1, qA + R);
    const int kBs = max(0, qB - R), kBe = min(SEQT - 1, qB + R);

    __syncthreads();

    // partial scores over this lane's 8 dims, union window [kAs, kBe], <=34 keys
    float scA[34], scB[34];
#pragma unroll
    for (int m = 0; m < 34; m++) {
        const int k = kAs + m;
        float dA = 0.0f, dB = 0.0f;
        if (k <= kBe) {
            const float* kr = &sK[(k - klo) * ATT_ROWPAD + lane8 * 8];
            float4 k0 = *(const float4*)kr;
            float4 k1 = *(const float4*)(kr + 4);
            dA = qFA[0]*k0.x + qFA[1]*k0.y + qFA[2]*k0.z + qFA[3]*k0.w
               + qFA[4]*k1.x + qFA[5]*k1.y + qFA[6]*k1.z + qFA[7]*k1.w;
            dB = qFB[0]*k0.x + qFB[1]*k0.y + qFB[2]*k0.z + qFB[3]*k0.w
               + qFB[4]*k1.x + qFB[5]*k1.y + qFB[6]*k1.z + qFB[7]*k1.w;
        }
        scA[m] = dA; scB[m] = dB;
    }

    // 8-lane butterfly all-reduce -> every lane has full scores
#pragma unroll
    for (int m = 0; m < 34; m++) {
        scA[m] += __shfl_xor_sync(0xffffffffu, scA[m], 1);
        scA[m] += __shfl_xor_sync(0xffffffffu, scA[m], 2);
        scA[m] += __shfl_xor_sync(0xffffffffu, scA[m], 4);
        scB[m] += __shfl_xor_sync(0xffffffffu, scB[m], 1);
        scB[m] += __shfl_xor_sync(0xffffffffu, scB[m], 2);
        scB[m] += __shfl_xor_sync(0xffffffffu, scB[m], 4);
    }

    // scale, mask, max
    const float NEGINF = -3.402823466e38f;
    float mA = NEGINF, mB = NEGINF;
#pragma unroll
    for (int m = 0; m < 34; m++) {
        const int k = kAs + m;
        scA[m] *= 0.125f;
        scB[m] *= 0.125f;
        if (k <= kAe)             mA = fmaxf(mA, scA[m]);
        if (k >= kBs && k <= kBe) mB = fmaxf(mB, scB[m]);
    }

    // exp in place (masked to 0), sum
    float sumA = 0.0f, sumB = 0.0f;
#pragma unroll
    for (int m = 0; m < 34; m++) {
        const int k = kAs + m;
        float eA = (k <= kAe)              ? __expf(scA[m] - mA) : 0.0f;
        float eB = (k >= kBs && k <= kBe)  ? __expf(scB[m] - mB) : 0.0f;
        scA[m] = eA; scB[m] = eB;
        sumA += eA; sumB += eB;
    }
    const float invA = 1.0f / sumA;
    const float invB = 1.0f / sumB;

    // PV: acc over union window
    float accA[8] = {0,0,0,0,0,0,0,0};
    float accB[8] = {0,0,0,0,0,0,0,0};
#pragma unroll
    for (int m = 0; m < 34; m++) {
        const int k = kAs + m;
        if (k <= kBe) {
            const float* vr = &sV[(k - klo) * ATT_ROWPAD + lane8 * 8];
            float4 v0 = *(const float4*)vr;
            float4 v1 = *(const float4*)(vr + 4);
            const float pA = scA[m] * invA;
            const float pB = scB[m] * invB;
            accA[0] += pA*v0.x; accA[1] += pA*v0.y; accA[2] += pA*v0.z; accA[3] += pA*v0.w;
            accA[4] += pA*v1.x; accA[5] += pA*v1.y; accA[6] += pA*v1.z; accA[7] += pA*v1.w;
            accB[0] += pB*v0.x; accB[1] += pB*v0.y; accB[2] += pB*v0.z; accB[3] += pB*v0.w;
            accB[4] += pB*v1.x; accB[5] += pB*v1.y; accB[6] += pB*v1.z; accB[7] += pB*v1.w;
        }
    }

    // write att as bf16 hi/lo (8 bf16 = one uint4 each)
    {
        uint4 hA, lA, hB, lB;
        __nv_bfloat16 hh, ll;
        uint32_t* ph = (uint32_t*)&hA; uint32_t* pl = (uint32_t*)&lA;
#pragma unroll
        for (int g = 0; g < 4; g++) {
            __nv_bfloat16 h0, l0, h1, l1;
            split_hilo(accA[g*2],   h0, l0);
            split_hilo(accA[g*2+1], h1, l1);
            ph[g] = pack_bf16x2(h0, h1);
            pl[g] = pack_bf16x2(l0, l1);
        }
        uint32_t* phb = (uint32_t*)&hB; uint32_t* plb = (uint32_t*)&lB;
#pragma unroll
        for (int g = 0; g < 4; g++) {
            __nv_bfloat16 h0, l0, h1, l1;
            split_hilo(accB[g*2],   h0, l0);
            split_hilo(accB[g*2+1], h1, l1);
            phb[g] = pack_bf16x2(h0, h1);
            plb[g] = pack_bf16x2(l0, l1);
        }
        (void)hh; (void)ll;
        size_t oA = ((size_t)(b * SEQT + qA)) * DMODEL + h * HD + lane8 * 8;
        size_t oB = ((size_t)(b * SEQT + qB)) * DMODEL + h * HD + lane8 * 8;
        *(uint4*)(atth + oA) = hA;
        *(uint4*)(attl + oA) = lA;
        *(uint4*)(atth + oB) = hB;
        *(uint4*)(attl + oB) = lB;
    }
}

// ---------------------------------------------------------------------------
extern "C" void kernel_launch(void* const* d_in, const int* in_sizes, int n_in,
                              void* d_out, int out_size)
{
    const float* x      = (const float*)d_in[0];
    const float* radius = (const float*)d_in[1];
    const float* w_in   = (const float*)d_in[2];
    const float* b_in   = (const float*)d_in[3];
    const float* w_out  = (const float*)d_in[4];
    const float* b_out  = (const float*)d_in[5];
    float* out = (float*)d_out;

    float *qkv;
    __nv_bfloat16 *xh, *xl, *wih, *wil, *woh, *wol, *atth, *attl;
    cudaGetSymbolAddress((void**)&qkv,  g_qkv);
    cudaGetSymbolAddress((void**)&xh,   g_xh);
    cudaGetSymbolAddress((void**)&xl,   g_xl);
    cudaGetSymbolAddress((void**)&wih,  g_wih);
    cudaGetSymbolAddress((void**)&wil,  g_wil);
    cudaGetSymbolAddress((void**)&woh,  g_woh);
    cudaGetSymbolAddress((void**)&wol,  g_wol);
    cudaGetSymbolAddress((void**)&atth, g_atth);
    cudaGetSymbolAddress((void**)&attl, g_attl);

    cudaFuncSetAttribute(tc_gemm_bf16,
                         cudaFuncAttributeMaxDynamicSharedMemorySize,
                         GEMM_SMEM_TOTAL);
    cudaFuncSetAttribute(band_attn_kernel,
                         cudaFuncAttributeMaxDynamicSharedMemorySize,
                         ATT_SMEM);

    // 0) fp32 -> bf16 hi/lo converts
    {
        int n4;
        n4 = (MROWS * DMODEL) / 4;
        cvt_hilo_kernel<<<(n4 + 255) / 256, 256>>>(x, xh, xl, n4);
        n4 = (THREE_D * DMODEL) / 4;
        cvt_hilo_kernel<<<(n4 + 255) / 256, 256>>>(w_in, wih, wil, n4);
        n4 = (DMODEL * DMODEL) / 4;
        cvt_hilo_kernel<<<(n4 + 255) / 256, 256>>>(w_out, woh, wol, n4);
    }

    // 1) QKV projection: [8192,512] x [1536,512]^T -> [8192,1536] fp32
    {
        dim3 grid(THREE_D / 128, MROWS / 128);
        tc_gemm_bf16<<<grid, 256, GEMM_SMEM_TOTAL>>>(
            xh, xl, wih, wil, b_in, qkv, MROWS, THREE_D, DMODEL);
    }

    // 2) Band attention -> att bf16 hi/lo
    {
        dim3 grid(SEQT / 64, NHEAD, BATCH);
        band_attn_kernel<<<grid, 256, ATT_SMEM>>>(qkv, radius, atth, attl);
    }

    // 3) Output projection: [8192,512] x [512,512]^T -> out fp32
    {
        dim3 grid(DMODEL / 128, MROWS / 128);
        tc_gemm_bf16<<<grid, 256, GEMM_SMEM_TOTAL>>>(
            atth, attl, woh, wol, b_out, out, MROWS, DMODEL, DMODEL);
    }
}